// round 14
// baseline (speedup 1.0000x reference)
#include <cuda_runtime.h>
#include <cuda_fp16.h>
#include <cstdint>

#define NN 100000
#define EE 1600000
#define NB_SCAN 98          // ceil(NN/1024)
#define G0_BLOCKS 782       // ceil(NN/128)
#define HIST_BLOCKS 64
#define GA0 260             // gemm0 tiles merged with hist (M1)
#define GB0 (G0_BLOCKS - GA0)
#define FILL_BLOCKS 128

// ---------------- scratch (__device__ globals; no allocation allowed) ------
// NOTE: never pass these as host-side kernel arguments (host shadow symbol !=
// device address; caused the 128MiB-delta guard trips in R3-R6).
__device__ int    g_cnt[NN];
__device__ int    g_rs[NN];
__device__ int    g_cur[NN];
__device__ int    g_bsum[NB_SCAN];
__device__ float  g_rinv1[NN];
__device__ float  g_rinv2[NN];
__device__ int    g_csr[EE];
__device__ __half g_w1t[128 * 128];          // W1 transposed [n][k] fp16
__device__ __half g_w2t[128 * 128];          // [W2s|W2n] transposed [n][k] fp16
__device__ __half g_y1h[(size_t)NN * 128];   // x @ W1 (fp16)
__device__ __half g_y2h[(size_t)NN * 64];    // h @ W2n (fp16)
__device__ float  g_z[(size_t)NN * 64];      // h @ W2s + b2 (fp32)

// ---------------------------------------------------------------------------
// helpers
// ---------------------------------------------------------------------------
__device__ __forceinline__ unsigned int h2u(float a, float b) {
    __half2 h = __float22half2_rn(make_float2(a, b));
    return *(unsigned int*)&h;
}
__device__ __forceinline__ void h2acc(unsigned int u, float& a, float& b) {
    __half2 h = *(__half2*)&u;
    float2 f = __half22float2(h);
    a += f.x; b += f.y;
}

#define MMA16816(c, a0, a1, a2, a3, b0, b1)                                  \
    asm volatile(                                                            \
        "mma.sync.aligned.m16n8k16.row.col.f32.f16.f16.f32 "                 \
        "{%0,%1,%2,%3}, {%4,%5,%6,%7}, {%8,%9}, {%0,%1,%2,%3};"              \
        : "+f"((c)[0]), "+f"((c)[1]), "+f"((c)[2]), "+f"((c)[3])             \
        : "r"(a0), "r"(a1), "r"(a2), "r"(a3), "r"(b0), "r"(b1))

#define SMH_STRIDE 136   // halfs per smem row (128 + 8 pad)
#define SMEM_MMA (2 * 128 * SMH_STRIDE * 2)   // As + Bs, bytes = 69632

// ---------------------------------------------------------------------------
// k_init: zero g_cnt + build fp16 transposed weights [n][k]
// ---------------------------------------------------------------------------
__global__ void k_init(const float* __restrict__ W1,
                       const float* __restrict__ W2s,
                       const float* __restrict__ W2n) {
    int i = blockIdx.x * 256 + threadIdx.x;
    if (i < NN) g_cnt[i] = 0;
    if (i < 16384) {
        int n = i >> 7, k = i & 127;
        g_w1t[i] = __float2half(W1[k * 128 + n]);
        g_w2t[i] = __float2half(n < 64 ? W2s[k * 64 + n] : W2n[k * 64 + (n - 64)]);
    }
}

// ---------------------------------------------------------------------------
// gemm0 tile (tensor core): y1h[128 x 128] = x_tile(fp16 cvt) @ W1
// 256 threads = 8 warps; warp = m32 x n64.
// ---------------------------------------------------------------------------
__device__ __forceinline__ void gemm0_tile(const float* __restrict__ x, int bid) {
    extern __shared__ __half smh[];
    __half* As = smh;                     // [row][k] 128 x 136
    __half* Bs = smh + 128 * SMH_STRIDE;  // [n][k]   128 x 136

    int tid = threadIdx.x;
    int r0 = bid * 128;

    for (int i = tid; i < 2048; i += 256) {
        int n = i >> 4, c = i & 15;
        *((uint4*)(Bs + n * SMH_STRIDE) + c) = *((const uint4*)g_w1t + n * 16 + c);
    }
    for (int i = tid; i < 4096; i += 256) {
        int r = i >> 5, c4 = i & 31;
        int gn = r0 + r;
        float4 v = make_float4(0.f, 0.f, 0.f, 0.f);
        if (gn < NN) v = ((const float4*)(x + (size_t)gn * 128))[c4];
        *((uint2*)(As + r * SMH_STRIDE + c4 * 4)) =
            make_uint2(h2u(v.x, v.y), h2u(v.z, v.w));
    }
    __syncthreads();

    int w = tid >> 5, lane = tid & 31, g = lane >> 2, q = lane & 3;
    int mg = w >> 1, ng = w & 1;
    int mrow = mg * 32;

    float c[2][8][4];
    #pragma unroll
    for (int mt = 0; mt < 2; mt++)
        #pragma unroll
        for (int nt = 0; nt < 8; nt++)
            #pragma unroll
            for (int j = 0; j < 4; j++) c[mt][nt][j] = 0.f;

    #pragma unroll
    for (int ks = 0; ks < 8; ks++) {
        int kb = ks * 16;
        unsigned int a[2][4];
        #pragma unroll
        for (int mt = 0; mt < 2; mt++) {
            const __half* ap = As + (mrow + mt * 16 + g) * SMH_STRIDE + kb + q * 2;
            a[mt][0] = *(const unsigned int*)ap;
            a[mt][1] = *(const unsigned int*)(ap + 8 * SMH_STRIDE);
            a[mt][2] = *(const unsigned int*)(ap + 8);
            a[mt][3] = *(const unsigned int*)(ap + 8 * SMH_STRIDE + 8);
        }
        #pragma unroll
        for (int nt = 0; nt < 8; nt++) {
            const __half* bp = Bs + (ng * 64 + nt * 8 + g) * SMH_STRIDE + kb + q * 2;
            unsigned int b0 = *(const unsigned int*)bp;
            unsigned int b1 = *(const unsigned int*)(bp + 8);
            MMA16816(c[0][nt], a[0][0], a[0][1], a[0][2], a[0][3], b0, b1);
            MMA16816(c[1][nt], a[1][0], a[1][1], a[1][2], a[1][3], b0, b1);
        }
    }

    #pragma unroll
    for (int mt = 0; mt < 2; mt++)
        #pragma unroll
        for (int nt = 0; nt < 8; nt++) {
            int row0 = r0 + mrow + mt * 16 + g;
            int col = ng * 64 + nt * 8 + q * 2;
            if (row0 < NN)
                *(unsigned int*)(g_y1h + (size_t)row0 * 128 + col) =
                    h2u(c[mt][nt][0], c[mt][nt][1]);
            if (row0 + 8 < NN)
                *(unsigned int*)(g_y1h + (size_t)(row0 + 8) * 128 + col) =
                    h2u(c[mt][nt][2], c[mt][nt][3]);
        }
}

// ---------------------------------------------------------------------------
// CSR build pieces
// ---------------------------------------------------------------------------
// M1: hist || gemm0 tiles [0, GA0)
__global__ void k_m1(const float* __restrict__ x, const int* __restrict__ dst) {
    if (blockIdx.x < HIST_BLOCKS) {
        for (int e = blockIdx.x * 256 + threadIdx.x; e < EE; e += HIST_BLOCKS * 256)
            atomicAdd(&g_cnt[__ldg(dst + e)], 1);
        return;
    }
    gemm0_tile(x, blockIdx.x - HIST_BLOCKS);
}

__global__ void k_scan1() {
    __shared__ int s[1024];
    int t = threadIdx.x;
    int i = blockIdx.x * 1024 + t;
    int v = (i < NN) ? g_cnt[i] : 0;
    s[t] = v;
    __syncthreads();
    #pragma unroll
    for (int off = 1; off < 1024; off <<= 1) {
        int u = (t >= off) ? s[t - off] : 0;
        __syncthreads();
        s[t] += u;
        __syncthreads();
    }
    if (i < NN) g_rs[i] = s[t] - v;
    if (t == 1023) g_bsum[blockIdx.x] = s[1023];
}

__global__ void k_scan3() {
    __shared__ int ws[4];
    __shared__ int sbs[NB_SCAN];
    int t = threadIdx.x;
    int lane = t & 31, wid = t >> 5;
    int v = 0, s = 0;
    if (t < 128) {
        v = (t < NB_SCAN) ? g_bsum[t] : 0;
        s = v;
        #pragma unroll
        for (int off = 1; off < 32; off <<= 1) {
            int u = __shfl_up_sync(0xffffffffu, s, off);
            if (lane >= off) s += u;
        }
        if (lane == 31) ws[wid] = s;
    }
    __syncthreads();
    if (t < NB_SCAN) {
        int add = 0;
        #pragma unroll
        for (int w = 0; w < 4; w++) add += (w < wid) ? ws[w] : 0;
        sbs[t] = s + add - v;
    }
    __syncthreads();
    int i = blockIdx.x * 256 + t;
    if (i >= NN) return;
    int rs = g_rs[i] + sbs[i >> 10];
    g_rs[i] = rs;
    g_cur[i] = rs;
    float c = (float)g_cnt[i];
    g_rinv1[i] = 1.f / (c + 1.f);
    g_rinv2[i] = 1.f / fmaxf(c, 1.f);
}

// M2: fill || gemm0 tiles [GA0, 782)
__global__ void k_m2(const float* __restrict__ x,
                     const int* __restrict__ src,
                     const int* __restrict__ dst) {
    if (blockIdx.x < FILL_BLOCKS) {
        for (int e = blockIdx.x * 256 + threadIdx.x; e < EE; e += FILL_BLOCKS * 256) {
            int d = __ldg(dst + e);
            int pos = atomicAdd(&g_cur[d], 1);
            g_csr[pos] = __ldg(src + e);
        }
        return;
    }
    gemm0_tile(x, blockIdx.x - FILL_BLOCKS + GA0);
}

// ---------------------------------------------------------------------------
// FUSED layer-1 aggregation + layer-2 GEMM.
// Block = 128 nodes. Phase 1: h rows built in smem As (fp16) via CSR gather:
//   h_i = relu((y1h_i + sum_j y1h_j)*rinv1 + b1)
// Phase 2: [z | y2h] = As @ g_w2t (m16n8k16 MMA), same epilogue as before.
// g_h global round-trip eliminated.
// ---------------------------------------------------------------------------
__global__ void k_l2fused(const float* __restrict__ b1,
                          const float* __restrict__ bias2) {
    extern __shared__ __half smh[];
    __half* As = smh;                     // [row][k] 128 x 136 (h tile)
    __half* Bs = smh + 128 * SMH_STRIDE;  // [n][k]   128 x 136

    int tid = threadIdx.x;
    int r0 = blockIdx.x * 128;

    // Bs <- g_w2t (independent of phase 1)
    for (int i = tid; i < 2048; i += 256) {
        int n = i >> 4, c = i & 15;
        *((uint4*)(Bs + n * SMH_STRIDE) + c) = *((const uint4*)g_w2t + n * 16 + c);
    }

    // Phase 1: aggregate h into As. Half-warp (16 lanes) per node, 8 nodes each.
    int hw = tid >> 4;        // 0..15
    int lane = tid & 15;      // covers cols lane*8..lane*8+7
    float4 bb0 = *(const float4*)(b1 + lane * 8);
    float4 bb1 = *(const float4*)(b1 + lane * 8 + 4);

    #pragma unroll 1
    for (int it = 0; it < 8; it++) {
        int r = it * 16 + hw;          // 0..127
        int w = r0 + r;
        uint4 o = make_uint4(0u, 0u, 0u, 0u);
        if (w < NN) {
            int beg = __ldg(g_rs + w);
            int cnt = __ldg(g_cnt + w);
            float rinv = __ldg(g_rinv1 + w);

            float acc[8] = {0.f, 0.f, 0.f, 0.f, 0.f, 0.f, 0.f, 0.f};
            {   // self
                uint4 rr = *(const uint4*)(g_y1h + (size_t)w * 128 + lane * 8);
                h2acc(rr.x, acc[0], acc[1]);
                h2acc(rr.y, acc[2], acc[3]);
                h2acc(rr.z, acc[4], acc[5]);
                h2acc(rr.w, acc[6], acc[7]);
            }
            int j = 0;
            for (; j + 8 <= cnt; j += 8) {
                int sidx[8];
                #pragma unroll
                for (int u = 0; u < 8; u++) sidx[u] = __ldg(g_csr + beg + j + u);
                uint4 rr[8];
                #pragma unroll
                for (int u = 0; u < 8; u++)
                    rr[u] = *(const uint4*)(g_y1h + (size_t)sidx[u] * 128 + lane * 8);
                #pragma unroll
                for (int u = 0; u < 8; u++) {
                    h2acc(rr[u].x, acc[0], acc[1]);
                    h2acc(rr[u].y, acc[2], acc[3]);
                    h2acc(rr[u].z, acc[4], acc[5]);
                    h2acc(rr[u].w, acc[6], acc[7]);
                }
            }
            for (; j < cnt; j++) {
                int s = __ldg(g_csr + beg + j);
                uint4 rr = *(const uint4*)(g_y1h + (size_t)s * 128 + lane * 8);
                h2acc(rr.x, acc[0], acc[1]);
                h2acc(rr.y, acc[2], acc[3]);
                h2acc(rr.z, acc[4], acc[5]);
                h2acc(rr.w, acc[6], acc[7]);
            }
            float v0 = fmaxf(acc[0] * rinv + bb0.x, 0.f);
            float v1 = fmaxf(acc[1] * rinv + bb0.y, 0.f);
            float v2 = fmaxf(acc[2] * rinv + bb0.z, 0.f);
            float v3 = fmaxf(acc[3] * rinv + bb0.w, 0.f);
            float v4 = fmaxf(acc[4] * rinv + bb1.x, 0.f);
            float v5 = fmaxf(acc[5] * rinv + bb1.y, 0.f);
            float v6 = fmaxf(acc[6] * rinv + bb1.z, 0.f);
            float v7 = fmaxf(acc[7] * rinv + bb1.w, 0.f);
            o.x = h2u(v0, v1); o.y = h2u(v2, v3);
            o.z = h2u(v4, v5); o.w = h2u(v6, v7);
        }
        *((uint4*)(As + r * SMH_STRIDE + lane * 8)) = o;
    }
    __syncthreads();

    // Phase 2: MMA
    int w8 = tid >> 5, l32 = tid & 31, g = l32 >> 2, q = l32 & 3;
    int mg = w8 >> 1, ng = w8 & 1;
    int mrow = mg * 32;

    float c[2][8][4];
    #pragma unroll
    for (int mt = 0; mt < 2; mt++)
        #pragma unroll
        for (int nt = 0; nt < 8; nt++)
            #pragma unroll
            for (int j = 0; j < 4; j++) c[mt][nt][j] = 0.f;

    #pragma unroll
    for (int ks = 0; ks < 8; ks++) {
        int kb = ks * 16;
        unsigned int a[2][4];
        #pragma unroll
        for (int mt = 0; mt < 2; mt++) {
            const __half* ap = As + (mrow + mt * 16 + g) * SMH_STRIDE + kb + q * 2;
            a[mt][0] = *(const unsigned int*)ap;
            a[mt][1] = *(const unsigned int*)(ap + 8 * SMH_STRIDE);
            a[mt][2] = *(const unsigned int*)(ap + 8);
            a[mt][3] = *(const unsigned int*)(ap + 8 * SMH_STRIDE + 8);
        }
        #pragma unroll
        for (int nt = 0; nt < 8; nt++) {
            const __half* bp = Bs + (ng * 64 + nt * 8 + g) * SMH_STRIDE + kb + q * 2;
            unsigned int b0 = *(const unsigned int*)bp;
            unsigned int b1v = *(const unsigned int*)(bp + 8);
            MMA16816(c[0][nt], a[0][0], a[0][1], a[0][2], a[0][3], b0, b1v);
            MMA16816(c[1][nt], a[1][0], a[1][1], a[1][2], a[1][3], b0, b1v);
        }
    }

    // epilogue: ng==0 -> z fp32 (+bias2); ng==1 -> y2h fp16
    #pragma unroll
    for (int mt = 0; mt < 2; mt++)
        #pragma unroll
        for (int nt = 0; nt < 8; nt++) {
            int row0 = r0 + mrow + mt * 16 + g;
            int col = ng * 64 + nt * 8 + q * 2;
            if (ng == 0) {
                float bz0 = __ldg(bias2 + col);
                float bz1 = __ldg(bias2 + col + 1);
                if (row0 < NN)
                    *(float2*)(g_z + (size_t)row0 * 64 + col) =
                        make_float2(c[mt][nt][0] + bz0, c[mt][nt][1] + bz1);
                if (row0 + 8 < NN)
                    *(float2*)(g_z + (size_t)(row0 + 8) * 64 + col) =
                        make_float2(c[mt][nt][2] + bz0, c[mt][nt][3] + bz1);
            } else {
                int c2 = col - 64;
                if (row0 < NN)
                    *(unsigned int*)(g_y2h + (size_t)row0 * 64 + c2) =
                        h2u(c[mt][nt][0], c[mt][nt][1]);
                if (row0 + 8 < NN)
                    *(unsigned int*)(g_y2h + (size_t)(row0 + 8) * 64 + c2) =
                        h2u(c[mt][nt][2], c[mt][nt][3]);
            }
        }
}

// ---------------------------------------------------------------------------
// Aggregation 2 + epilogue: out = z + (sum_j y2h_j) * rinv2
// 8 lanes per node (16B fp16 per neighbor row).
// ---------------------------------------------------------------------------
__global__ __launch_bounds__(256) void k_agg2out(float* __restrict__ out) {
    int w = blockIdx.x * 32 + (threadIdx.x >> 3);
    if (w >= NN) return;
    int lane = threadIdx.x & 7;
    int beg = __ldg(g_rs + w);
    int cnt = __ldg(g_cnt + w);
    float rinv = __ldg(g_rinv2 + w);

    float acc[8] = {0.f, 0.f, 0.f, 0.f, 0.f, 0.f, 0.f, 0.f};
    int j = 0;
    for (; j + 8 <= cnt; j += 8) {
        int sidx[8];
        #pragma unroll
        for (int u = 0; u < 8; u++) sidx[u] = __ldg(g_csr + beg + j + u);
        uint4 r[8];
        #pragma unroll
        for (int u = 0; u < 8; u++)
            r[u] = *(const uint4*)(g_y2h + (size_t)sidx[u] * 64 + lane * 8);
        #pragma unroll
        for (int u = 0; u < 8; u++) {
            h2acc(r[u].x, acc[0], acc[1]);
            h2acc(r[u].y, acc[2], acc[3]);
            h2acc(r[u].z, acc[4], acc[5]);
            h2acc(r[u].w, acc[6], acc[7]);
        }
    }
    for (; j < cnt; j++) {
        int s = __ldg(g_csr + beg + j);
        uint4 r = *(const uint4*)(g_y2h + (size_t)s * 64 + lane * 8);
        h2acc(r.x, acc[0], acc[1]);
        h2acc(r.y, acc[2], acc[3]);
        h2acc(r.z, acc[4], acc[5]);
        h2acc(r.w, acc[6], acc[7]);
    }

    float4 z0 = *(const float4*)(g_z + (size_t)w * 64 + lane * 8);
    float4 z1 = *(const float4*)(g_z + (size_t)w * 64 + lane * 8 + 4);
    float4 o0, o1;
    o0.x = z0.x + acc[0] * rinv;
    o0.y = z0.y + acc[1] * rinv;
    o0.z = z0.z + acc[2] * rinv;
    o0.w = z0.w + acc[3] * rinv;
    o1.x = z1.x + acc[4] * rinv;
    o1.y = z1.y + acc[5] * rinv;
    o1.z = z1.z + acc[6] * rinv;
    o1.w = z1.w + acc[7] * rinv;
    *((float4*)(out + (size_t)w * 64 + lane * 8)) = o0;
    *((float4*)(out + (size_t)w * 64 + lane * 8 + 4)) = o1;
}

// ---------------------------------------------------------------------------
extern "C" void kernel_launch(void* const* d_in, const int* in_sizes, int n_in,
                              void* d_out, int out_size) {
    const float* x   = (const float*)d_in[0];
    const float* W1  = (const float*)d_in[1];
    const float* b1  = (const float*)d_in[2];
    const float* W2n = (const float*)d_in[3];
    const float* W2s = (const float*)d_in[4];
    const float* b2  = (const float*)d_in[5];
    const int*   ei  = (const int*)d_in[6];
    const int* src = ei;
    const int* dst = ei + EE;

    cudaFuncSetAttribute(k_m1, cudaFuncAttributeMaxDynamicSharedMemorySize, SMEM_MMA);
    cudaFuncSetAttribute(k_m2, cudaFuncAttributeMaxDynamicSharedMemorySize, SMEM_MMA);
    cudaFuncSetAttribute(k_l2fused, cudaFuncAttributeMaxDynamicSharedMemorySize, SMEM_MMA);

    k_init<<<(NN + 255) / 256, 256>>>(W1, W2s, W2n);
    k_m1<<<HIST_BLOCKS + GA0, 256, SMEM_MMA>>>(x, dst);          // hist || gemm0 A
    k_scan1<<<NB_SCAN, 1024>>>();
    k_scan3<<<(NN + 255) / 256, 256>>>();
    k_m2<<<FILL_BLOCKS + GB0, 256, SMEM_MMA>>>(x, src, dst);     // fill || gemm0 B
    k_l2fused<<<G0_BLOCKS, 256, SMEM_MMA>>>(b1, b2);             // agg1 + gemm1 fused
    k_agg2out<<<(NN + 31) / 32, 256>>>((float*)d_out);
}

// round 16
// speedup vs baseline: 1.0630x; 1.0630x over previous
#include <cuda_runtime.h>
#include <cuda_fp16.h>
#include <cstdint>

#define NN 100000
#define EE 1600000
#define NB_SCAN 98          // ceil(NN/1024)
#define G0_BLOCKS 782       // ceil(NN/128)
#define HIST_BLOCKS 64
#define GA0 260             // gemm0 tiles merged with hist (M1)
#define GB0 (G0_BLOCKS - GA0)
#define FILL_BLOCKS 128

// ---------------- scratch (__device__ globals; no allocation allowed) ------
// NOTE: never pass these as host-side kernel arguments (host shadow symbol !=
// device address; caused the 128MiB-delta guard trips in R3-R6).
__device__ int    g_cnt[NN];
__device__ int    g_rs[NN];
__device__ int    g_cur[NN];
__device__ int    g_bsum[NB_SCAN];
__device__ float  g_rinv1[NN];
__device__ float  g_rinv2[NN];
__device__ int    g_csr[EE];
__device__ __half g_w1t[128 * 128];          // W1 transposed [n][k] fp16
__device__ __half g_w2t[128 * 128];          // [W2s|W2n] transposed [n][k] fp16
__device__ __half g_y1h[(size_t)NN * 128];   // x @ W1 (fp16)
__device__ __half g_h[(size_t)NN * 128];     // hidden activations (fp16)
__device__ __half g_y2h[(size_t)NN * 64];    // h @ W2n (fp16)
__device__ float  g_z[(size_t)NN * 64];      // h @ W2s + b2 (fp32)

// ---------------------------------------------------------------------------
// helpers
// ---------------------------------------------------------------------------
__device__ __forceinline__ unsigned int h2u(float a, float b) {
    __half2 h = __float22half2_rn(make_float2(a, b));
    return *(unsigned int*)&h;
}
__device__ __forceinline__ void h2acc(unsigned int u, float& a, float& b) {
    __half2 h = *(__half2*)&u;
    float2 f = __half22float2(h);
    a += f.x; b += f.y;
}

#define MMA16816(c, a0, a1, a2, a3, b0, b1)                                  \
    asm volatile(                                                            \
        "mma.sync.aligned.m16n8k16.row.col.f32.f16.f16.f32 "                 \
        "{%0,%1,%2,%3}, {%4,%5,%6,%7}, {%8,%9}, {%0,%1,%2,%3};"              \
        : "+f"((c)[0]), "+f"((c)[1]), "+f"((c)[2]), "+f"((c)[3])             \
        : "r"(a0), "r"(a1), "r"(a2), "r"(a3), "r"(b0), "r"(b1))

#define SMH_STRIDE 136   // halfs per smem row (128 + 8 pad)
#define SMEM_MMA (2 * 128 * SMH_STRIDE * 2)   // As + Bs, bytes = 69632

// ---------------------------------------------------------------------------
// k_init: zero g_cnt + build fp16 transposed weights [n][k]
// ---------------------------------------------------------------------------
__global__ void k_init(const float* __restrict__ W1,
                       const float* __restrict__ W2s,
                       const float* __restrict__ W2n) {
    int i = blockIdx.x * 256 + threadIdx.x;
    if (i < NN) g_cnt[i] = 0;
    if (i < 16384) {
        int n = i >> 7, k = i & 127;
        g_w1t[i] = __float2half(W1[k * 128 + n]);
        g_w2t[i] = __float2half(n < 64 ? W2s[k * 64 + n] : W2n[k * 64 + (n - 64)]);
    }
}

// ---------------------------------------------------------------------------
// gemm0 tile (tensor core): y1h[128 x 128] = x_tile(fp16 cvt) @ W1
// 256 threads = 8 warps; warp = m32 x n64.
// ---------------------------------------------------------------------------
__device__ __forceinline__ void gemm0_tile(const float* __restrict__ x, int bid) {
    extern __shared__ __half smh[];
    __half* As = smh;                     // [row][k] 128 x 136
    __half* Bs = smh + 128 * SMH_STRIDE;  // [n][k]   128 x 136

    int tid = threadIdx.x;
    int r0 = bid * 128;

    for (int i = tid; i < 2048; i += 256) {
        int n = i >> 4, c = i & 15;
        *((uint4*)(Bs + n * SMH_STRIDE) + c) = *((const uint4*)g_w1t + n * 16 + c);
    }
    for (int i = tid; i < 4096; i += 256) {
        int r = i >> 5, c4 = i & 31;
        int gn = r0 + r;
        float4 v = make_float4(0.f, 0.f, 0.f, 0.f);
        if (gn < NN) v = ((const float4*)(x + (size_t)gn * 128))[c4];
        *((uint2*)(As + r * SMH_STRIDE + c4 * 4)) =
            make_uint2(h2u(v.x, v.y), h2u(v.z, v.w));
    }
    __syncthreads();

    int w = tid >> 5, lane = tid & 31, g = lane >> 2, q = lane & 3;
    int mg = w >> 1, ng = w & 1;
    int mrow = mg * 32;

    float c[2][8][4];
    #pragma unroll
    for (int mt = 0; mt < 2; mt++)
        #pragma unroll
        for (int nt = 0; nt < 8; nt++)
            #pragma unroll
            for (int j = 0; j < 4; j++) c[mt][nt][j] = 0.f;

    #pragma unroll
    for (int ks = 0; ks < 8; ks++) {
        int kb = ks * 16;
        unsigned int a[2][4];
        #pragma unroll
        for (int mt = 0; mt < 2; mt++) {
            const __half* ap = As + (mrow + mt * 16 + g) * SMH_STRIDE + kb + q * 2;
            a[mt][0] = *(const unsigned int*)ap;
            a[mt][1] = *(const unsigned int*)(ap + 8 * SMH_STRIDE);
            a[mt][2] = *(const unsigned int*)(ap + 8);
            a[mt][3] = *(const unsigned int*)(ap + 8 * SMH_STRIDE + 8);
        }
        #pragma unroll
        for (int nt = 0; nt < 8; nt++) {
            const __half* bp = Bs + (ng * 64 + nt * 8 + g) * SMH_STRIDE + kb + q * 2;
            unsigned int b0 = *(const unsigned int*)bp;
            unsigned int b1 = *(const unsigned int*)(bp + 8);
            MMA16816(c[0][nt], a[0][0], a[0][1], a[0][2], a[0][3], b0, b1);
            MMA16816(c[1][nt], a[1][0], a[1][1], a[1][2], a[1][3], b0, b1);
        }
    }

    #pragma unroll
    for (int mt = 0; mt < 2; mt++)
        #pragma unroll
        for (int nt = 0; nt < 8; nt++) {
            int row0 = r0 + mrow + mt * 16 + g;
            int col = ng * 64 + nt * 8 + q * 2;
            if (row0 < NN)
                *(unsigned int*)(g_y1h + (size_t)row0 * 128 + col) =
                    h2u(c[mt][nt][0], c[mt][nt][1]);
            if (row0 + 8 < NN)
                *(unsigned int*)(g_y1h + (size_t)(row0 + 8) * 128 + col) =
                    h2u(c[mt][nt][2], c[mt][nt][3]);
        }
}

// ---------------------------------------------------------------------------
// CSR build pieces
// ---------------------------------------------------------------------------
// M1: hist || gemm0 tiles [0, GA0)
__global__ void k_m1(const float* __restrict__ x, const int* __restrict__ dst) {
    if (blockIdx.x < HIST_BLOCKS) {
        for (int e = blockIdx.x * 256 + threadIdx.x; e < EE; e += HIST_BLOCKS * 256)
            atomicAdd(&g_cnt[__ldg(dst + e)], 1);
        return;
    }
    gemm0_tile(x, blockIdx.x - HIST_BLOCKS);
}

__global__ void k_scan1() {
    __shared__ int s[1024];
    int t = threadIdx.x;
    int i = blockIdx.x * 1024 + t;
    int v = (i < NN) ? g_cnt[i] : 0;
    s[t] = v;
    __syncthreads();
    #pragma unroll
    for (int off = 1; off < 1024; off <<= 1) {
        int u = (t >= off) ? s[t - off] : 0;
        __syncthreads();
        s[t] += u;
        __syncthreads();
    }
    if (i < NN) g_rs[i] = s[t] - v;
    if (t == 1023) g_bsum[blockIdx.x] = s[1023];
}

__global__ void k_scan3() {
    __shared__ int ws[4];
    __shared__ int sbs[NB_SCAN];
    int t = threadIdx.x;
    int lane = t & 31, wid = t >> 5;
    int v = 0, s = 0;
    if (t < 128) {
        v = (t < NB_SCAN) ? g_bsum[t] : 0;
        s = v;
        #pragma unroll
        for (int off = 1; off < 32; off <<= 1) {
            int u = __shfl_up_sync(0xffffffffu, s, off);
            if (lane >= off) s += u;
        }
        if (lane == 31) ws[wid] = s;
    }
    __syncthreads();
    if (t < NB_SCAN) {
        int add = 0;
        #pragma unroll
        for (int w = 0; w < 4; w++) add += (w < wid) ? ws[w] : 0;
        sbs[t] = s + add - v;
    }
    __syncthreads();
    int i = blockIdx.x * 256 + t;
    if (i >= NN) return;
    int rs = g_rs[i] + sbs[i >> 10];
    g_rs[i] = rs;
    g_cur[i] = rs;
    float c = (float)g_cnt[i];
    g_rinv1[i] = 1.f / (c + 1.f);
    g_rinv2[i] = 1.f / fmaxf(c, 1.f);
}

// M2: fill || gemm0 tiles [GA0, 782)
__global__ void k_m2(const float* __restrict__ x,
                     const int* __restrict__ src,
                     const int* __restrict__ dst) {
    if (blockIdx.x < FILL_BLOCKS) {
        for (int e = blockIdx.x * 256 + threadIdx.x; e < EE; e += FILL_BLOCKS * 256) {
            int d = __ldg(dst + e);
            int pos = atomicAdd(&g_cur[d], 1);
            g_csr[pos] = __ldg(src + e);
        }
        return;
    }
    gemm0_tile(x, blockIdx.x - FILL_BLOCKS + GA0);
}

// ---------------------------------------------------------------------------
// Aggregation 1: h_i = relu((y1h_i + sum_j y1h_j)*rinv1 + b1), fp16 out
// Half-warp per node: 16 lanes x 8 cols (16B fp16/lane). High-occupancy
// standalone kernel (fusing this into the smem-heavy MMA kernel regressed:
// gather is latency-bound and needs warps in flight — R14 lesson).
// ---------------------------------------------------------------------------
__global__ __launch_bounds__(256) void k_agg1b(const float* __restrict__ b1) {
    int w = blockIdx.x * 16 + (threadIdx.x >> 4);
    if (w >= NN) return;
    int lane = threadIdx.x & 15;
    int beg = __ldg(g_rs + w);
    int cnt = __ldg(g_cnt + w);
    float rinv = __ldg(g_rinv1 + w);

    float acc[8] = {0.f, 0.f, 0.f, 0.f, 0.f, 0.f, 0.f, 0.f};
    {   // self (fp16)
        uint4 r = *(const uint4*)(g_y1h + (size_t)w * 128 + lane * 8);
        h2acc(r.x, acc[0], acc[1]);
        h2acc(r.y, acc[2], acc[3]);
        h2acc(r.z, acc[4], acc[5]);
        h2acc(r.w, acc[6], acc[7]);
    }

    int j = 0;
    for (; j + 8 <= cnt; j += 8) {
        int sidx[8];
        #pragma unroll
        for (int u = 0; u < 8; u++) sidx[u] = __ldg(g_csr + beg + j + u);
        uint4 r[8];
        #pragma unroll
        for (int u = 0; u < 8; u++)
            r[u] = *(const uint4*)(g_y1h + (size_t)sidx[u] * 128 + lane * 8);
        #pragma unroll
        for (int u = 0; u < 8; u++) {
            h2acc(r[u].x, acc[0], acc[1]);
            h2acc(r[u].y, acc[2], acc[3]);
            h2acc(r[u].z, acc[4], acc[5]);
            h2acc(r[u].w, acc[6], acc[7]);
        }
    }
    for (; j < cnt; j++) {
        int s = __ldg(g_csr + beg + j);
        uint4 r = *(const uint4*)(g_y1h + (size_t)s * 128 + lane * 8);
        h2acc(r.x, acc[0], acc[1]);
        h2acc(r.y, acc[2], acc[3]);
        h2acc(r.z, acc[4], acc[5]);
        h2acc(r.w, acc[6], acc[7]);
    }

    float4 bb0 = *(const float4*)(b1 + lane * 8);
    float4 bb1 = *(const float4*)(b1 + lane * 8 + 4);
    float v0 = fmaxf(acc[0] * rinv + bb0.x, 0.f);
    float v1 = fmaxf(acc[1] * rinv + bb0.y, 0.f);
    float v2 = fmaxf(acc[2] * rinv + bb0.z, 0.f);
    float v3 = fmaxf(acc[3] * rinv + bb0.w, 0.f);
    float v4 = fmaxf(acc[4] * rinv + bb1.x, 0.f);
    float v5 = fmaxf(acc[5] * rinv + bb1.y, 0.f);
    float v6 = fmaxf(acc[6] * rinv + bb1.z, 0.f);
    float v7 = fmaxf(acc[7] * rinv + bb1.w, 0.f);
    uint4 o;
    o.x = h2u(v0, v1); o.y = h2u(v2, v3);
    o.z = h2u(v4, v5); o.w = h2u(v6, v7);
    *((uint4*)(g_h + (size_t)w * 128 + lane * 8)) = o;
}

// ---------------------------------------------------------------------------
// Layer-2 GEMM (tensor core): z(fp32,+b2) = h@W2s ; y2h(fp16) = h@W2n
// ---------------------------------------------------------------------------
__global__ void k_gemm1(const float* __restrict__ bias) {
    extern __shared__ __half smh[];
    __half* As = smh;
    __half* Bs = smh + 128 * SMH_STRIDE;

    int tid = threadIdx.x;
    int r0 = blockIdx.x * 128;

    for (int i = tid; i < 2048; i += 256) {
        int n = i >> 4, c = i & 15;
        *((uint4*)(Bs + n * SMH_STRIDE) + c) = *((const uint4*)g_w2t + n * 16 + c);
    }
    for (int i = tid; i < 2048; i += 256) {
        int r = i >> 4, c = i & 15;
        int gn = r0 + r;
        uint4 v = make_uint4(0u, 0u, 0u, 0u);
        if (gn < NN) v = *((const uint4*)(g_h + (size_t)gn * 128) + c);
        *((uint4*)(As + r * SMH_STRIDE) + c) = v;
    }
    __syncthreads();

    int w = tid >> 5, lane = tid & 31, g = lane >> 2, q = lane & 3;
    int mg = w >> 1, ng = w & 1;
    int mrow = mg * 32;

    float c[2][8][4];
    #pragma unroll
    for (int mt = 0; mt < 2; mt++)
        #pragma unroll
        for (int nt = 0; nt < 8; nt++)
            #pragma unroll
            for (int j = 0; j < 4; j++) c[mt][nt][j] = 0.f;

    #pragma unroll
    for (int ks = 0; ks < 8; ks++) {
        int kb = ks * 16;
        unsigned int a[2][4];
        #pragma unroll
        for (int mt = 0; mt < 2; mt++) {
            const __half* ap = As + (mrow + mt * 16 + g) * SMH_STRIDE + kb + q * 2;
            a[mt][0] = *(const unsigned int*)ap;
            a[mt][1] = *(const unsigned int*)(ap + 8 * SMH_STRIDE);
            a[mt][2] = *(const unsigned int*)(ap + 8);
            a[mt][3] = *(const unsigned int*)(ap + 8 * SMH_STRIDE + 8);
        }
        #pragma unroll
        for (int nt = 0; nt < 8; nt++) {
            const __half* bp = Bs + (ng * 64 + nt * 8 + g) * SMH_STRIDE + kb + q * 2;
            unsigned int b0 = *(const unsigned int*)bp;
            unsigned int b1 = *(const unsigned int*)(bp + 8);
            MMA16816(c[0][nt], a[0][0], a[0][1], a[0][2], a[0][3], b0, b1);
            MMA16816(c[1][nt], a[1][0], a[1][1], a[1][2], a[1][3], b0, b1);
        }
    }

    // epilogue: ng==0 -> z fp32 (+bias); ng==1 -> y2h fp16
    #pragma unroll
    for (int mt = 0; mt < 2; mt++)
        #pragma unroll
        for (int nt = 0; nt < 8; nt++) {
            int row0 = r0 + mrow + mt * 16 + g;
            int col = ng * 64 + nt * 8 + q * 2;
            if (ng == 0) {
                float bz0 = __ldg(bias + col);
                float bz1 = __ldg(bias + col + 1);
                if (row0 < NN)
                    *(float2*)(g_z + (size_t)row0 * 64 + col) =
                        make_float2(c[mt][nt][0] + bz0, c[mt][nt][1] + bz1);
                if (row0 + 8 < NN)
                    *(float2*)(g_z + (size_t)(row0 + 8) * 64 + col) =
                        make_float2(c[mt][nt][2] + bz0, c[mt][nt][3] + bz1);
            } else {
                int c2 = col - 64;
                if (row0 < NN)
                    *(unsigned int*)(g_y2h + (size_t)row0 * 64 + c2) =
                        h2u(c[mt][nt][0], c[mt][nt][1]);
                if (row0 + 8 < NN)
                    *(unsigned int*)(g_y2h + (size_t)(row0 + 8) * 64 + c2) =
                        h2u(c[mt][nt][2], c[mt][nt][3]);
            }
        }
}

// ---------------------------------------------------------------------------
// Aggregation 2 + epilogue: out = z + (sum_j y2h_j) * rinv2
// 8 lanes per node (16B fp16 per neighbor row).
// ---------------------------------------------------------------------------
__global__ __launch_bounds__(256) void k_agg2out(float* __restrict__ out) {
    int w = blockIdx.x * 32 + (threadIdx.x >> 3);
    if (w >= NN) return;
    int lane = threadIdx.x & 7;
    int beg = __ldg(g_rs + w);
    int cnt = __ldg(g_cnt + w);
    float rinv = __ldg(g_rinv2 + w);

    float acc[8] = {0.f, 0.f, 0.f, 0.f, 0.f, 0.f, 0.f, 0.f};
    int j = 0;
    for (; j + 8 <= cnt; j += 8) {
        int sidx[8];
        #pragma unroll
        for (int u = 0; u < 8; u++) sidx[u] = __ldg(g_csr + beg + j + u);
        uint4 r[8];
        #pragma unroll
        for (int u = 0; u < 8; u++)
            r[u] = *(const uint4*)(g_y2h + (size_t)sidx[u] * 64 + lane * 8);
        #pragma unroll
        for (int u = 0; u < 8; u++) {
            h2acc(r[u].x, acc[0], acc[1]);
            h2acc(r[u].y, acc[2], acc[3]);
            h2acc(r[u].z, acc[4], acc[5]);
            h2acc(r[u].w, acc[6], acc[7]);
        }
    }
    for (; j < cnt; j++) {
        int s = __ldg(g_csr + beg + j);
        uint4 r = *(const uint4*)(g_y2h + (size_t)s * 64 + lane * 8);
        h2acc(r.x, acc[0], acc[1]);
        h2acc(r.y, acc[2], acc[3]);
        h2acc(r.z, acc[4], acc[5]);
        h2acc(r.w, acc[6], acc[7]);
    }

    float4 z0 = *(const float4*)(g_z + (size_t)w * 64 + lane * 8);
    float4 z1 = *(const float4*)(g_z + (size_t)w * 64 + lane * 8 + 4);
    float4 o0, o1;
    o0.x = z0.x + acc[0] * rinv;
    o0.y = z0.y + acc[1] * rinv;
    o0.z = z0.z + acc[2] * rinv;
    o0.w = z0.w + acc[3] * rinv;
    o1.x = z1.x + acc[4] * rinv;
    o1.y = z1.y + acc[5] * rinv;
    o1.z = z1.z + acc[6] * rinv;
    o1.w = z1.w + acc[7] * rinv;
    *((float4*)(out + (size_t)w * 64 + lane * 8)) = o0;
    *((float4*)(out + (size_t)w * 64 + lane * 8 + 4)) = o1;
}

// ---------------------------------------------------------------------------
extern "C" void kernel_launch(void* const* d_in, const int* in_sizes, int n_in,
                              void* d_out, int out_size) {
    const float* x   = (const float*)d_in[0];
    const float* W1  = (const float*)d_in[1];
    const float* b1  = (const float*)d_in[2];
    const float* W2n = (const float*)d_in[3];
    const float* W2s = (const float*)d_in[4];
    const float* b2  = (const float*)d_in[5];
    const int*   ei  = (const int*)d_in[6];
    const int* src = ei;
    const int* dst = ei + EE;

    cudaFuncSetAttribute(k_m1, cudaFuncAttributeMaxDynamicSharedMemorySize, SMEM_MMA);
    cudaFuncSetAttribute(k_m2, cudaFuncAttributeMaxDynamicSharedMemorySize, SMEM_MMA);
    cudaFuncSetAttribute(k_gemm1, cudaFuncAttributeMaxDynamicSharedMemorySize, SMEM_MMA);

    k_init<<<(NN + 255) / 256, 256>>>(W1, W2s, W2n);
    k_m1<<<HIST_BLOCKS + GA0, 256, SMEM_MMA>>>(x, dst);          // hist || gemm0 A
    k_scan1<<<NB_SCAN, 1024>>>();
    k_scan3<<<(NN + 255) / 256, 256>>>();
    k_m2<<<FILL_BLOCKS + GB0, 256, SMEM_MMA>>>(x, src, dst);     // fill || gemm0 B
    k_agg1b<<<(NN + 15) / 16, 256>>>(b1);
    k_gemm1<<<G0_BLOCKS, 256, SMEM_MMA>>>(b2);
    k_agg2out<<<(NN + 31) / 32, 256>>>((float*)d_out);
}